// round 3
// baseline (speedup 1.0000x reference)
#include <cuda_runtime.h>
#include <cstdint>

// ---------------------------------------------------------------------------
// Model constants
// ---------------------------------------------------------------------------
#define Bn    16
#define Ln    1024
#define Cin   21
#define Cout  21
#define DM    512
#define DIN   1024
#define DS    16
#define DTR   32
#define PRED  96
#define TST   928          // Ln - PRED

// ---------------------------------------------------------------------------
// Scratch layout (floats). Single static device buffer — no allocations.
// ---------------------------------------------------------------------------
#define O_PE     ((size_t)0)                       // 1024*512
#define O_MEAN   (O_PE   + 524288)                 // 512 (336 used)
#define O_STD    (O_MEAN + 512)
#define O_RSTD   (O_STD  + 512)
#define O_WOHT   (O_RSTD + 512)                    // 21*1024 transposed fold
#define O_XNW    (O_WOHT + 21504)                  // 16*1026*21 = 344736
#define O_AEMB   (O_XNW  + 344736)                 // 16384*80
#define O_BEMB   (O_AEMB + 1310720)                // 80*512
#define O_EMB    (O_BEMB + 40960)                  // 16384*512
#define O_UPRE   (O_EMB  + 8388608)                // 16384*1024
#define O_U      (O_UPRE + 16777216)               // 16384*1024
#define O_Z      (O_U    + 16777216)               // 1536*1024
#define O_XDBL   (O_Z    + 1572864)                // 16384*64
#define O_DTL    (O_XDBL + 1048576)                // 16384*1024
#define O_Y      (O_DTL  + 16777216)               // 1536*1024
#define SCRATCH_TOTAL (O_Y + 1572864)

__device__ __align__(16) float g_scratch[SCRATCH_TOTAL];

// ---------------------------------------------------------------------------
// Positional embedding table [1024, 512]
// ---------------------------------------------------------------------------
__global__ void pe_kernel(float* __restrict__ pe) {
    int idx = blockIdx.x * blockDim.x + threadIdx.x;
    if (idx >= Ln * DM) return;
    int l = idx / DM, d = idx - l * DM;
    float div = expf((float)(d & ~1) * (-0.017988946039015984f)); // -log(1e4)/512
    float v = (float)l * div;
    pe[idx] = (d & 1) ? cosf(v) : sinf(v);
}

// ---------------------------------------------------------------------------
// RevIN stats: mean / std / 1/std per (b, c). 336 blocks x 128 threads.
// ---------------------------------------------------------------------------
__global__ void stats_kernel(const float* __restrict__ x, float* __restrict__ meanv,
                             float* __restrict__ stdv, float* __restrict__ rstd) {
    int bc = blockIdx.x;            // b*21 + c
    int b = bc / Cin, c = bc - b * Cin;
    const float* p = x + (size_t)b * Ln * Cin + c;
    float s = 0.f, s2 = 0.f;
    for (int l = threadIdx.x; l < Ln; l += 128) {
        float v = p[(size_t)l * Cin];
        s += v;
        s2 = fmaf(v, v, s2);
    }
#pragma unroll
    for (int o = 16; o; o >>= 1) {
        s  += __shfl_xor_sync(0xffffffffu, s, o);
        s2 += __shfl_xor_sync(0xffffffffu, s2, o);
    }
    __shared__ float sh[2][4];
    int w = threadIdx.x >> 5;
    if ((threadIdx.x & 31) == 0) { sh[0][w] = s; sh[1][w] = s2; }
    __syncthreads();
    if (threadIdx.x == 0) {
        s  = sh[0][0] + sh[0][1] + sh[0][2] + sh[0][3];
        s2 = sh[1][0] + sh[1][1] + sh[1][2] + sh[1][3];
        float m   = s * (1.f / Ln);
        float var = s2 * (1.f / Ln) - m * m;
        float sd  = sqrtf(var + 1e-5f);
        meanv[bc] = m;
        stdv[bc]  = sd;
        rstd[bc]  = 1.f / sd;
    }
}

// ---------------------------------------------------------------------------
// Fold W_out[1024,512] @ W_head[512,21] -> wohT[21,1024] (transposed)
// 84 blocks x 256 threads, one thread per (k,c)
// ---------------------------------------------------------------------------
__global__ void woh_kernel(const float* __restrict__ Wout, const float* __restrict__ Whead,
                           float* __restrict__ wohT) {
    int idx = blockIdx.x * 256 + threadIdx.x;   // 0..21503
    if (idx >= DIN * Cout) return;
    int k = idx / Cout, c = idx - k * Cout;
    const float* wr = Wout + (size_t)k * DM;
    float s = 0.f;
    for (int j = 0; j < DM; j++) s = fmaf(wr[j], Whead[(size_t)j * Cout + c], s);
    wohT[(size_t)c * DIN + k] = s;
}

// ---------------------------------------------------------------------------
// Normalize into wrap-padded buffer xnw [B, 1026, 21]
// row r in xnw corresponds to original l = r-1; row 0 = l=L-1, row L+1 = l=0.
// ---------------------------------------------------------------------------
__global__ void normalize_kernel(const float* __restrict__ x,
                                 const float* __restrict__ meanv,
                                 const float* __restrict__ rstd,
                                 float* __restrict__ xnw) {
    int idx = blockIdx.x * 256 + threadIdx.x;   // B*L*Cin = 344064
    if (idx >= Bn * Ln * Cin) return;
    int c = idx % Cin;
    int l = (idx / Cin) % Ln;
    int b = idx / (Cin * Ln);
    float v = (x[idx] - meanv[b * Cin + c]) * rstd[b * Cin + c];
    float* base = xnw + (size_t)b * (Ln + 2) * Cin;
    base[(size_t)(l + 1) * Cin + c] = v;
    if (l == 0)       base[(size_t)(Ln + 1) * Cin + c] = v;
    if (l == Ln - 1)  base[c] = v;
}

// ---------------------------------------------------------------------------
// Build Aemb [16384, 80]: [xn window(63) | mark(4) | zeros(13)]
// ---------------------------------------------------------------------------
__global__ void aemb_kernel(const float* __restrict__ xnw,
                            const float* __restrict__ mark,
                            float* __restrict__ Aemb) {
    int idx = blockIdx.x * 256 + threadIdx.x;   // 16384*80 = 1310720
    if (idx >= Bn * Ln * 80) return;
    int j = idx % 80;
    int m = idx / 80;
    int l = m & 1023, b = m >> 10;
    float v;
    if (j < 63)      v = xnw[((size_t)b * (Ln + 2) + l) * Cin + j];
    else if (j < 67) v = mark[(size_t)m * 4 + (j - 63)];
    else             v = 0.f;
    Aemb[idx] = v;
}

// ---------------------------------------------------------------------------
// Build Bemb [80, 512]: rows 0..62 = conv_tok_w flat [63,512], 63..66 = time_w,
// 67..79 = 0.
// ---------------------------------------------------------------------------
__global__ void bemb_kernel(const float* __restrict__ ctw,
                            const float* __restrict__ tw,
                            float* __restrict__ Bemb) {
    int idx = blockIdx.x * 256 + threadIdx.x;   // 80*512 = 40960
    if (idx >= 80 * DM) return;
    int r = idx / DM, col = idx - r * DM;
    float v;
    if (r < 63)      v = ctw[idx];
    else if (r < 67) v = tw[(size_t)(r - 63) * DM + col];
    else             v = 0.f;
    Bemb[idx] = v;
}

// ---------------------------------------------------------------------------
// Generic SGEMM: C[M,N] = gatherRows(A)[M,K] @ B[K,N]  (+bias, +pe)
// BM=128, BN=64, BK=16, 256 threads, 8x4 micro-tile.
// Requires: M % 128 == 0, N % 64 == 0, K % 16 == 0, lda % 4 == 0.
// A row remap: ar = (m/gsz)*gstr + goff + m%gsz   (gsz=1<<30,goff=0,gstr=0 => identity)
// mode bit0: add bias[col]; bit1: add pe[(row&1023)*512 + col] (only for N==512 full)
// ---------------------------------------------------------------------------
__global__ void __launch_bounds__(256) sgemm_kernel(
    const float* __restrict__ A, int lda,
    const float* __restrict__ B, int ldb,
    float* __restrict__ C, int ldc,
    int K,
    const float* __restrict__ bias,
    const float* __restrict__ pe,
    int mode, int gsz, int goff, int gstr)
{
    __shared__ float As[16][132];
    __shared__ float Bs[16][64];
    int tid = threadIdx.x;
    int m0 = blockIdx.y * 128;
    int n0 = blockIdx.x * 64;
    int tx = tid & 15, ty = tid >> 4;

    float acc[8][4];
#pragma unroll
    for (int i = 0; i < 8; i++)
#pragma unroll
        for (int j = 0; j < 4; j++) acc[i][j] = 0.f;

    // Per-thread A load rows (fixed across k-tiles)
    const float* Arow[2];
    int c4s[2];
#pragma unroll
    for (int i = 0; i < 2; i++) {
        int idx = tid + i * 256;
        int row = idx >> 2;
        c4s[i] = idx & 3;
        int grow = m0 + row;
        int q = grow / gsz;
        int ar = q * gstr + goff + (grow - q * gsz);
        Arow[i] = A + (size_t)ar * lda;
    }
    int brow = tid >> 4, bc4 = tid & 15;

    for (int k0 = 0; k0 < K; k0 += 16) {
        // Stage A (transposed) and B tiles
#pragma unroll
        for (int i = 0; i < 2; i++) {
            int idx = tid + i * 256;
            int row = idx >> 2;
            float4 v = *(const float4*)(Arow[i] + k0 + c4s[i] * 4);
            As[c4s[i] * 4 + 0][row] = v.x;
            As[c4s[i] * 4 + 1][row] = v.y;
            As[c4s[i] * 4 + 2][row] = v.z;
            As[c4s[i] * 4 + 3][row] = v.w;
        }
        *(float4*)&Bs[brow][bc4 * 4] =
            *(const float4*)(B + (size_t)(k0 + brow) * ldb + n0 + bc4 * 4);
        __syncthreads();

#pragma unroll
        for (int k = 0; k < 16; k++) {
            float4 a0 = *(const float4*)&As[k][ty * 8];
            float4 a1 = *(const float4*)&As[k][ty * 8 + 4];
            float4 bb = *(const float4*)&Bs[k][tx * 4];
            float av[8] = {a0.x, a0.y, a0.z, a0.w, a1.x, a1.y, a1.z, a1.w};
            float bv[4] = {bb.x, bb.y, bb.z, bb.w};
#pragma unroll
            for (int i = 0; i < 8; i++)
#pragma unroll
                for (int j = 0; j < 4; j++)
                    acc[i][j] = fmaf(av[i], bv[j], acc[i][j]);
        }
        __syncthreads();
    }

    // Epilogue
    int ncol = n0 + tx * 4;
    float bv[4] = {0.f, 0.f, 0.f, 0.f};
    if (mode & 1) {
#pragma unroll
        for (int j = 0; j < 4; j++) bv[j] = bias[ncol + j];
    }
#pragma unroll
    for (int i = 0; i < 8; i++) {
        int row = m0 + ty * 8 + i;
        float4 o;
        o.x = acc[i][0] + bv[0];
        o.y = acc[i][1] + bv[1];
        o.z = acc[i][2] + bv[2];
        o.w = acc[i][3] + bv[3];
        if (mode & 2) {
            const float* per = pe + (size_t)(row & 1023) * 512 + ncol;
            o.x += per[0]; o.y += per[1]; o.z += per[2]; o.w += per[3];
        }
        *(float4*)(C + (size_t)row * ldc + ncol) = o;
    }
}

// ---------------------------------------------------------------------------
// Depthwise causal conv (k=4) + SiLU: u_pre -> u
// 512 blocks x 256 threads; each thread: one (b, d), 128 timesteps.
// ---------------------------------------------------------------------------
__global__ void __launch_bounds__(256) dwconv_kernel(
    const float* __restrict__ up, const float* __restrict__ w,
    const float* __restrict__ bvec, float* __restrict__ out)
{
    int tid = threadIdx.x;
    int blk = blockIdx.x;
    int dchunk = blk & 3;
    int lc = (blk >> 2) & 7;
    int b = blk >> 5;
    int d = dchunk * 256 + tid;
    float4 wv = *(const float4*)(w + (size_t)d * 4);
    float bias = bvec[d];
    int l0 = lc * 128;
    const float* base = up + (size_t)b * Ln * DIN + d;
    float* obase = out + (size_t)b * Ln * DIN + d;
    float x0, x1, x2;
    if (l0 == 0) { x0 = 0.f; x1 = 0.f; x2 = 0.f; }
    else {
        x0 = base[(size_t)(l0 - 3) * DIN];
        x1 = base[(size_t)(l0 - 2) * DIN];
        x2 = base[(size_t)(l0 - 1) * DIN];
    }
#pragma unroll 4
    for (int l = l0; l < l0 + 128; l++) {
        float xin = base[(size_t)l * DIN];
        float a = fmaf(wv.x, x0, fmaf(wv.y, x1, fmaf(wv.z, x2, fmaf(wv.w, xin, bias))));
        obase[(size_t)l * DIN] = __fdividef(a, 1.f + __expf(-a));
        x0 = x1; x1 = x2; x2 = xin;
    }
}

// ---------------------------------------------------------------------------
// Selective scan + skip + gating. 4 threads per channel (4 states each).
// 256 blocks x 256 threads. Emits gated y only for t >= 928 into Y[1536,1024].
// ---------------------------------------------------------------------------
__device__ __forceinline__ float softplus_f(float x) {
    return (x > 20.f) ? x : __logf(1.f + __expf(x));
}

__global__ void __launch_bounds__(256) scan_kernel(
    const float* __restrict__ u, const float* __restrict__ dtl,
    const float* __restrict__ xdbl, const float* __restrict__ A_log,
    const float* __restrict__ Dw, const float* __restrict__ z,
    float* __restrict__ Y)
{
    int tid = threadIdx.x;
    int b = blockIdx.x >> 4;
    int d = ((blockIdx.x & 15) << 6) + (tid >> 2);
    int sg = tid & 3;                       // states sg*4 .. sg*4+3

    float A0 = -__expf(A_log[(size_t)d * DS + sg * 4 + 0]);
    float A1 = -__expf(A_log[(size_t)d * DS + sg * 4 + 1]);
    float A2 = -__expf(A_log[(size_t)d * DS + sg * 4 + 2]);
    float A3 = -__expf(A_log[(size_t)d * DS + sg * 4 + 3]);
    float Dv = Dw[d];

    const float* ub = u   + (size_t)b * Ln * DIN + d;
    const float* db = dtl + (size_t)b * Ln * DIN + d;
    const float* xb = xdbl + (size_t)b * Ln * 64;

    float h0 = 0.f, h1 = 0.f, h2 = 0.f, h3 = 0.f;

#pragma unroll 4
    for (int t = 0; t < TST; t++) {
        float uv = __ldg(ub + (size_t)t * DIN);
        float dv = __ldg(db + (size_t)t * DIN);
        float4 Bv = *(const float4*)(xb + (size_t)t * 64 + 32 + sg * 4);
        float dt = softplus_f(dv);
        float dtu = dt * uv;
        h0 = fmaf(h0, __expf(dt * A0), dtu * Bv.x);
        h1 = fmaf(h1, __expf(dt * A1), dtu * Bv.y);
        h2 = fmaf(h2, __expf(dt * A2), dtu * Bv.z);
        h3 = fmaf(h3, __expf(dt * A3), dtu * Bv.w);
    }
#pragma unroll 2
    for (int t = TST; t < Ln; t++) {
        float uv = __ldg(ub + (size_t)t * DIN);
        float dv = __ldg(db + (size_t)t * DIN);
        float4 Bv = *(const float4*)(xb + (size_t)t * 64 + 32 + sg * 4);
        float dt = softplus_f(dv);
        float dtu = dt * uv;
        h0 = fmaf(h0, __expf(dt * A0), dtu * Bv.x);
        h1 = fmaf(h1, __expf(dt * A1), dtu * Bv.y);
        h2 = fmaf(h2, __expf(dt * A2), dtu * Bv.z);
        h3 = fmaf(h3, __expf(dt * A3), dtu * Bv.w);
        float4 Cv = *(const float4*)(xb + (size_t)t * 64 + 48 + sg * 4);
        float y = fmaf(h0, Cv.x, fmaf(h1, Cv.y, fmaf(h2, Cv.z, h3 * Cv.w)));
        y += __shfl_xor_sync(0xffffffffu, y, 1);
        y += __shfl_xor_sync(0xffffffffu, y, 2);
        if (sg == 0) {
            int i = t - TST;
            size_t oidx = ((size_t)b * PRED + i) * DIN + d;
            float zv = z[oidx];
            float g = __fdividef(zv, 1.f + __expf(-zv));   // silu(z)
            Y[oidx] = (y + uv * Dv) * g;
        }
    }
}

// ---------------------------------------------------------------------------
// Head: out[b,i,c] = (Y[b,i,:] . wohT[c,:]) * std[b,c] + mean[b,c]
// block per (b,i); 21 warps (672 threads), one warp per c.
// ---------------------------------------------------------------------------
__global__ void head_kernel(const float* __restrict__ Y, const float* __restrict__ wohT,
                            const float* __restrict__ stdv, const float* __restrict__ meanv,
                            float* __restrict__ out)
{
    int bi = blockIdx.x;                // 0..1535 = b*96 + i
    int b = bi / PRED;
    int c = threadIdx.x >> 5;           // 0..20
    int lane = threadIdx.x & 31;
    const float* yr = Y + (size_t)bi * DIN;
    const float* wr = wohT + (size_t)c * DIN;
    float s = 0.f;
#pragma unroll 4
    for (int k = lane; k < DIN; k += 32) s = fmaf(yr[k], wr[k], s);
#pragma unroll
    for (int o = 16; o; o >>= 1) s += __shfl_xor_sync(0xffffffffu, s, o);
    if (lane == 0)
        out[(size_t)bi * Cout + c] = s * stdv[b * Cin + c] + meanv[b * Cin + c];
}

// ---------------------------------------------------------------------------
// Launch
// ---------------------------------------------------------------------------
extern "C" void kernel_launch(void* const* d_in, const int* in_sizes, int n_in,
                              void* d_out, int out_size)
{
    const float* x_enc   = (const float*)d_in[0];
    const float* x_mark  = (const float*)d_in[1];
    const float* ctw     = (const float*)d_in[2];   // [3,21,512]
    const float* tw      = (const float*)d_in[3];   // [4,512]
    const float* W_in    = (const float*)d_in[4];   // [512,2048]
    const float* conv_w  = (const float*)d_in[5];   // [1024,4]
    const float* conv_b  = (const float*)d_in[6];   // [1024]
    const float* W_xproj = (const float*)d_in[7];   // [1024,64]
    const float* W_dt    = (const float*)d_in[8];   // [32,1024]
    const float* b_dt    = (const float*)d_in[9];   // [1024]
    const float* A_log   = (const float*)d_in[10];  // [1024,16]
    const float* Dw      = (const float*)d_in[11];  // [1024]
    const float* W_out   = (const float*)d_in[12];  // [1024,512]
    const float* W_head  = (const float*)d_in[13];  // [512,21]
    float* out = (float*)d_out;

    float* S;
    cudaGetSymbolAddress((void**)&S, g_scratch);
    float* pe    = S + O_PE;
    float* meanv = S + O_MEAN;
    float* stdv  = S + O_STD;
    float* rstd  = S + O_RSTD;
    float* wohT  = S + O_WOHT;
    float* xnw   = S + O_XNW;
    float* Aemb  = S + O_AEMB;
    float* Bemb  = S + O_BEMB;
    float* emb   = S + O_EMB;
    float* u_pre = S + O_UPRE;
    float* u     = S + O_U;
    float* zbuf  = S + O_Z;
    float* xdbl  = S + O_XDBL;
    float* dtl   = S + O_DTL;
    float* Ybuf  = S + O_Y;

    const int IDENT = 1 << 30;

    // Preprocessing
    pe_kernel<<<2048, 256>>>(pe);
    stats_kernel<<<Bn * Cin, 128>>>(x_enc, meanv, stdv, rstd);
    woh_kernel<<<84, 256>>>(W_out, W_head, wohT);
    normalize_kernel<<<1344, 256>>>(x_enc, meanv, rstd, xnw);
    aemb_kernel<<<5120, 256>>>(xnw, x_mark, Aemb);
    bemb_kernel<<<160, 256>>>(ctw, tw, Bemb);

    // emb = Aemb[16384,80] @ Bemb[80,512] + PE   (token conv + time emb fused)
    sgemm_kernel<<<dim3(512 / 64, 16384 / 128), 256>>>(
        Aemb, 80, Bemb, 512, emb, 512, 80, nullptr, pe, 2, IDENT, 0, 0);

    // u_pre = emb @ W_in[:, :1024]
    sgemm_kernel<<<dim3(1024 / 64, 16384 / 128), 256>>>(
        emb, 512, W_in, 2048, u_pre, 1024, 512, nullptr, nullptr, 0, IDENT, 0, 0);

    // z (last 96 rows per batch) = emb_gathered @ W_in[:, 1024:]
    sgemm_kernel<<<dim3(1024 / 64, 1536 / 128), 256>>>(
        emb, 512, W_in + 1024, 2048, zbuf, 1024, 512, nullptr, nullptr, 0,
        PRED, TST, Ln);

    // depthwise causal conv + SiLU
    dwconv_kernel<<<512, 256>>>(u_pre, conv_w, conv_b, u);

    // x_dbl = u @ W_xproj
    sgemm_kernel<<<dim3(64 / 64, 16384 / 128), 256>>>(
        u, 1024, W_xproj, 64, xdbl, 64, 1024, nullptr, nullptr, 0, IDENT, 0, 0);

    // dt logits = dtr @ W_dt + b_dt   (dtr = first 32 cols of x_dbl)
    sgemm_kernel<<<dim3(1024 / 64, 16384 / 128), 256>>>(
        xdbl, 64, W_dt, 1024, dtl, 1024, 32, b_dt, nullptr, 1, IDENT, 0, 0);

    // selective scan + skip + SiLU(z) gating -> Y [1536, 1024]
    scan_kernel<<<256, 256>>>(u, dtl, xdbl, A_log, Dw, zbuf, Ybuf);

    // head: (Y @ (W_out@W_head)) * std + mean
    head_kernel<<<1536, 672>>>(Ybuf, wohT, stdv, meanv, out);
}

// round 4
// speedup vs baseline: 1.3048x; 1.3048x over previous
#include <cuda_runtime.h>
#include <cstdint>

// ---------------------------------------------------------------------------
// Model constants
// ---------------------------------------------------------------------------
#define Bn    16
#define Ln    1024
#define Cin   21
#define Cout  21
#define DM    512
#define DIN   1024
#define DS    16
#define DTR   32
#define PRED  96
#define TST   928          // Ln - PRED

// ---------------------------------------------------------------------------
// Scratch layout (floats). Single static device buffer — no allocations.
// ---------------------------------------------------------------------------
#define O_PE     ((size_t)0)                       // 1024*512
#define O_MEAN   (O_PE   + 524288)                 // 512 (336 used)
#define O_STD    (O_MEAN + 512)
#define O_RSTD   (O_STD  + 512)
#define O_WOHT   (O_RSTD + 512)                    // 21*1024 transposed fold
#define O_XNW    (O_WOHT + 21504)                  // 16*1026*21 = 344736
#define O_AEMB   (O_XNW  + 344736)                 // 16384*80
#define O_BEMB   (O_AEMB + 1310720)                // 80*512
#define O_EMB    (O_BEMB + 40960)                  // 16384*512
#define O_UPRE   (O_EMB  + 8388608)                // 16384*1024
#define O_U      (O_UPRE + 16777216)               // 16384*1024
#define O_Z      (O_U    + 16777216)               // 1536*1024
#define O_XDBL   (O_Z    + 1572864)                // 16384*64
#define O_DTL    (O_XDBL + 1048576)                // 16384*1024
#define O_Y      (O_DTL  + 16777216)               // 1536*1024
#define SCRATCH_TOTAL (O_Y + 1572864)

__device__ __align__(16) float g_scratch[SCRATCH_TOTAL];

// ---------------------------------------------------------------------------
// Positional embedding table [1024, 512]
// ---------------------------------------------------------------------------
__global__ void pe_kernel(float* __restrict__ pe) {
    int idx = blockIdx.x * blockDim.x + threadIdx.x;
    if (idx >= Ln * DM) return;
    int l = idx / DM, d = idx - l * DM;
    float div = expf((float)(d & ~1) * (-0.017988946039015984f)); // -log(1e4)/512
    float v = (float)l * div;
    pe[idx] = (d & 1) ? cosf(v) : sinf(v);
}

// ---------------------------------------------------------------------------
// RevIN stats: mean / std / 1/std per (b, c). 336 blocks x 128 threads.
// ---------------------------------------------------------------------------
__global__ void stats_kernel(const float* __restrict__ x, float* __restrict__ meanv,
                             float* __restrict__ stdv, float* __restrict__ rstd) {
    int bc = blockIdx.x;            // b*21 + c
    int b = bc / Cin, c = bc - b * Cin;
    const float* p = x + (size_t)b * Ln * Cin + c;
    float s = 0.f, s2 = 0.f;
    for (int l = threadIdx.x; l < Ln; l += 128) {
        float v = p[(size_t)l * Cin];
        s += v;
        s2 = fmaf(v, v, s2);
    }
#pragma unroll
    for (int o = 16; o; o >>= 1) {
        s  += __shfl_xor_sync(0xffffffffu, s, o);
        s2 += __shfl_xor_sync(0xffffffffu, s2, o);
    }
    __shared__ float sh[2][4];
    int w = threadIdx.x >> 5;
    if ((threadIdx.x & 31) == 0) { sh[0][w] = s; sh[1][w] = s2; }
    __syncthreads();
    if (threadIdx.x == 0) {
        s  = sh[0][0] + sh[0][1] + sh[0][2] + sh[0][3];
        s2 = sh[1][0] + sh[1][1] + sh[1][2] + sh[1][3];
        float m   = s * (1.f / Ln);
        float var = s2 * (1.f / Ln) - m * m;
        float sd  = sqrtf(var + 1e-5f);
        meanv[bc] = m;
        stdv[bc]  = sd;
        rstd[bc]  = 1.f / sd;
    }
}

// ---------------------------------------------------------------------------
// Fold W_out[1024,512] @ W_head[512,21] -> wohT[21,1024] (transposed)
// ---------------------------------------------------------------------------
__global__ void woh_kernel(const float* __restrict__ Wout, const float* __restrict__ Whead,
                           float* __restrict__ wohT) {
    int idx = blockIdx.x * 256 + threadIdx.x;   // 0..21503
    if (idx >= DIN * Cout) return;
    int k = idx / Cout, c = idx - k * Cout;
    const float* wr = Wout + (size_t)k * DM;
    float s = 0.f;
    for (int j = 0; j < DM; j++) s = fmaf(wr[j], Whead[(size_t)j * Cout + c], s);
    wohT[(size_t)c * DIN + k] = s;
}

// ---------------------------------------------------------------------------
// Normalize into wrap-padded buffer xnw [B, 1026, 21]
// ---------------------------------------------------------------------------
__global__ void normalize_kernel(const float* __restrict__ x,
                                 const float* __restrict__ meanv,
                                 const float* __restrict__ rstd,
                                 float* __restrict__ xnw) {
    int idx = blockIdx.x * 256 + threadIdx.x;   // B*L*Cin = 344064
    if (idx >= Bn * Ln * Cin) return;
    int c = idx % Cin;
    int l = (idx / Cin) % Ln;
    int b = idx / (Cin * Ln);
    float v = (x[idx] - meanv[b * Cin + c]) * rstd[b * Cin + c];
    float* base = xnw + (size_t)b * (Ln + 2) * Cin;
    base[(size_t)(l + 1) * Cin + c] = v;
    if (l == 0)       base[(size_t)(Ln + 1) * Cin + c] = v;
    if (l == Ln - 1)  base[c] = v;
}

// ---------------------------------------------------------------------------
// Build Aemb [16384, 80]: [xn window(63) | mark(4) | zeros(13)]
// ---------------------------------------------------------------------------
__global__ void aemb_kernel(const float* __restrict__ xnw,
                            const float* __restrict__ mark,
                            float* __restrict__ Aemb) {
    int idx = blockIdx.x * 256 + threadIdx.x;   // 16384*80 = 1310720
    if (idx >= Bn * Ln * 80) return;
    int j = idx % 80;
    int m = idx / 80;
    int l = m & 1023, b = m >> 10;
    float v;
    if (j < 63)      v = xnw[((size_t)b * (Ln + 2) + l) * Cin + j];
    else if (j < 67) v = mark[(size_t)m * 4 + (j - 63)];
    else             v = 0.f;
    Aemb[idx] = v;
}

// ---------------------------------------------------------------------------
// Build Bemb [80, 512]
// ---------------------------------------------------------------------------
__global__ void bemb_kernel(const float* __restrict__ ctw,
                            const float* __restrict__ tw,
                            float* __restrict__ Bemb) {
    int idx = blockIdx.x * 256 + threadIdx.x;   // 80*512 = 40960
    if (idx >= 80 * DM) return;
    int r = idx / DM, col = idx - r * DM;
    float v;
    if (r < 63)      v = ctw[idx];
    else if (r < 67) v = tw[(size_t)(r - 63) * DM + col];
    else             v = 0.f;
    Bemb[idx] = v;
}

// ---------------------------------------------------------------------------
// Generic fp32 SGEMM (for the small GEMMs): BM=128, BN=64, BK=16
// ---------------------------------------------------------------------------
__global__ void __launch_bounds__(256) sgemm_kernel(
    const float* __restrict__ A, int lda,
    const float* __restrict__ B, int ldb,
    float* __restrict__ C, int ldc,
    int K,
    const float* __restrict__ bias,
    const float* __restrict__ pe,
    int mode, int gsz, int goff, int gstr)
{
    __shared__ float As[16][132];
    __shared__ float Bs[16][64];
    int tid = threadIdx.x;
    int m0 = blockIdx.y * 128;
    int n0 = blockIdx.x * 64;
    int tx = tid & 15, ty = tid >> 4;

    float acc[8][4];
#pragma unroll
    for (int i = 0; i < 8; i++)
#pragma unroll
        for (int j = 0; j < 4; j++) acc[i][j] = 0.f;

    const float* Arow[2];
    int c4s[2];
#pragma unroll
    for (int i = 0; i < 2; i++) {
        int idx = tid + i * 256;
        int row = idx >> 2;
        c4s[i] = idx & 3;
        int grow = m0 + row;
        int q = grow / gsz;
        int ar = q * gstr + goff + (grow - q * gsz);
        Arow[i] = A + (size_t)ar * lda;
    }
    int brow = tid >> 4, bc4 = tid & 15;

    for (int k0 = 0; k0 < K; k0 += 16) {
#pragma unroll
        for (int i = 0; i < 2; i++) {
            int idx = tid + i * 256;
            int row = idx >> 2;
            float4 v = *(const float4*)(Arow[i] + k0 + c4s[i] * 4);
            As[c4s[i] * 4 + 0][row] = v.x;
            As[c4s[i] * 4 + 1][row] = v.y;
            As[c4s[i] * 4 + 2][row] = v.z;
            As[c4s[i] * 4 + 3][row] = v.w;
        }
        *(float4*)&Bs[brow][bc4 * 4] =
            *(const float4*)(B + (size_t)(k0 + brow) * ldb + n0 + bc4 * 4);
        __syncthreads();

#pragma unroll
        for (int k = 0; k < 16; k++) {
            float4 a0 = *(const float4*)&As[k][ty * 8];
            float4 a1 = *(const float4*)&As[k][ty * 8 + 4];
            float4 bb = *(const float4*)&Bs[k][tx * 4];
            float av[8] = {a0.x, a0.y, a0.z, a0.w, a1.x, a1.y, a1.z, a1.w};
            float bv[4] = {bb.x, bb.y, bb.z, bb.w};
#pragma unroll
            for (int i = 0; i < 8; i++)
#pragma unroll
                for (int j = 0; j < 4; j++)
                    acc[i][j] = fmaf(av[i], bv[j], acc[i][j]);
        }
        __syncthreads();
    }

    int ncol = n0 + tx * 4;
    float bv[4] = {0.f, 0.f, 0.f, 0.f};
    if (mode & 1) {
#pragma unroll
        for (int j = 0; j < 4; j++) bv[j] = bias[ncol + j];
    }
#pragma unroll
    for (int i = 0; i < 8; i++) {
        int row = m0 + ty * 8 + i;
        float4 o;
        o.x = acc[i][0] + bv[0];
        o.y = acc[i][1] + bv[1];
        o.z = acc[i][2] + bv[2];
        o.w = acc[i][3] + bv[3];
        if (mode & 2) {
            const float* per = pe + (size_t)(row & 1023) * 512 + ncol;
            o.x += per[0]; o.y += per[1]; o.z += per[2]; o.w += per[3];
        }
        *(float4*)(C + (size_t)row * ldc + ncol) = o;
    }
}

// ---------------------------------------------------------------------------
// TF32 tensor-core GEMM: C[M,N] = gatherRows(A)[M,K] @ B[K,N]
// BM=128, BN=128, BK=16, 256 threads (8 warps, 2x4), warp tile 64x32.
// mma.sync.m16n8k8 tf32, fp32 accumulate. Double-buffered smem.
// Requires M%128==0, N%128==0, K%16==0.
// ---------------------------------------------------------------------------
__device__ __forceinline__ unsigned f2tf32(float f) {
    unsigned u;
    asm("cvt.rna.tf32.f32 %0, %1;" : "=r"(u) : "f"(f));
    return u;
}

__device__ __forceinline__ void mma_tf32(float* c, const unsigned* a, const unsigned* b) {
    asm volatile(
        "mma.sync.aligned.m16n8k8.row.col.f32.tf32.tf32.f32 "
        "{%0,%1,%2,%3}, {%4,%5,%6,%7}, {%8,%9}, {%0,%1,%2,%3};\n"
        : "+f"(c[0]), "+f"(c[1]), "+f"(c[2]), "+f"(c[3])
        : "r"(a[0]), "r"(a[1]), "r"(a[2]), "r"(a[3]),
          "r"(b[0]), "r"(b[1]));
}

__global__ void __launch_bounds__(256) tf32_gemm_kernel(
    const float* __restrict__ A, int lda,
    const float* __restrict__ B, int ldb,
    float* __restrict__ C, int ldc,
    int K, int gsz, int goff, int gstr)
{
    // As: [buf][m=128][k=16+pad4] stride 20 (fragment reads conflict-free)
    // Bs: [buf][k=16][n=128+pad8] stride 136 (fragment reads conflict-free)
    __shared__ unsigned As[2][128][20];
    __shared__ unsigned Bs[2][16][136];

    int tid  = threadIdx.x;
    int lane = tid & 31;
    int wid  = tid >> 5;
    int warp_m = (wid & 1) * 64;
    int warp_n = (wid >> 1) * 32;
    int m0 = blockIdx.y * 128;
    int n0 = blockIdx.x * 128;

    // staging coordinates (fixed across k-tiles)
    const float* Arow[2];
    int arow_[2], akq_[2];
    int bkr_[2], bn_[2];
#pragma unroll
    for (int i = 0; i < 2; i++) {
        int idx = tid + i * 256;
        int row = idx >> 2, kq = idx & 3;
        int grow = m0 + row;
        int q = grow / gsz;
        int ar = q * gstr + goff + (grow - q * gsz);
        Arow[i] = A + (size_t)ar * lda + kq * 4;
        arow_[i] = row; akq_[i] = kq;
        bkr_[i] = idx >> 5;            // 0..15
        bn_[i]  = (idx & 31) * 4;      // 0..124
    }

    float acc[4][4][4];
#pragma unroll
    for (int mi = 0; mi < 4; mi++)
#pragma unroll
        for (int ni = 0; ni < 4; ni++)
#pragma unroll
            for (int r = 0; r < 4; r++) acc[mi][ni][r] = 0.f;

    int NT = K >> 4;
    float4 fa[2], fb[2];

    // prefetch tile 0
#pragma unroll
    for (int i = 0; i < 2; i++) {
        fa[i] = *(const float4*)(Arow[i]);
        fb[i] = *(const float4*)(B + (size_t)bkr_[i] * ldb + n0 + bn_[i]);
    }
    // stage into buf 0
#pragma unroll
    for (int i = 0; i < 2; i++) {
        uint4 ua = {f2tf32(fa[i].x), f2tf32(fa[i].y), f2tf32(fa[i].z), f2tf32(fa[i].w)};
        *(uint4*)&As[0][arow_[i]][akq_[i] * 4] = ua;
        uint4 ub = {f2tf32(fb[i].x), f2tf32(fb[i].y), f2tf32(fb[i].z), f2tf32(fb[i].w)};
        *(uint4*)&Bs[0][bkr_[i]][bn_[i]] = ub;
    }
    __syncthreads();

    for (int kt = 0; kt < NT; kt++) {
        int cur = kt & 1;
        if (kt + 1 < NT) {
            int k0 = (kt + 1) * 16;
#pragma unroll
            for (int i = 0; i < 2; i++) {
                fa[i] = *(const float4*)(Arow[i] + k0);
                fb[i] = *(const float4*)(B + (size_t)(k0 + bkr_[i]) * ldb + n0 + bn_[i]);
            }
        }
#pragma unroll
        for (int ks = 0; ks < 2; ks++) {
            int kk = ks * 8;
            unsigned afr[4][4], bfr[4][2];
#pragma unroll
            for (int mi = 0; mi < 4; mi++) {
                int r = warp_m + mi * 16 + (lane >> 2);
                int kc = kk + (lane & 3);
                afr[mi][0] = As[cur][r][kc];
                afr[mi][1] = As[cur][r + 8][kc];
                afr[mi][2] = As[cur][r][kc + 4];
                afr[mi][3] = As[cur][r + 8][kc + 4];
            }
#pragma unroll
            for (int ni = 0; ni < 4; ni++) {
                int cn = warp_n + ni * 8 + (lane >> 2);
                int kr = kk + (lane & 3);
                bfr[ni][0] = Bs[cur][kr][cn];
                bfr[ni][1] = Bs[cur][kr + 4][cn];
            }
#pragma unroll
            for (int mi = 0; mi < 4; mi++)
#pragma unroll
                for (int ni = 0; ni < 4; ni++)
                    mma_tf32(acc[mi][ni], afr[mi], bfr[ni]);
        }
        if (kt + 1 < NT) {
            int nb = (kt + 1) & 1;
#pragma unroll
            for (int i = 0; i < 2; i++) {
                uint4 ua = {f2tf32(fa[i].x), f2tf32(fa[i].y), f2tf32(fa[i].z), f2tf32(fa[i].w)};
                *(uint4*)&As[nb][arow_[i]][akq_[i] * 4] = ua;
                uint4 ub = {f2tf32(fb[i].x), f2tf32(fb[i].y), f2tf32(fb[i].z), f2tf32(fb[i].w)};
                *(uint4*)&Bs[nb][bkr_[i]][bn_[i]] = ub;
            }
        }
        __syncthreads();
    }

    // epilogue
#pragma unroll
    for (int mi = 0; mi < 4; mi++) {
        int r = m0 + warp_m + mi * 16 + (lane >> 2);
#pragma unroll
        for (int ni = 0; ni < 4; ni++) {
            int cc = n0 + warp_n + ni * 8 + 2 * (lane & 3);
            float2 lo = {acc[mi][ni][0], acc[mi][ni][1]};
            float2 hi = {acc[mi][ni][2], acc[mi][ni][3]};
            *(float2*)(C + (size_t)r * ldc + cc) = lo;
            *(float2*)(C + (size_t)(r + 8) * ldc + cc) = hi;
        }
    }
}

// ---------------------------------------------------------------------------
// Depthwise causal conv (k=4) + SiLU: u_pre -> u
// ---------------------------------------------------------------------------
__global__ void __launch_bounds__(256) dwconv_kernel(
    const float* __restrict__ up, const float* __restrict__ w,
    const float* __restrict__ bvec, float* __restrict__ out)
{
    int tid = threadIdx.x;
    int blk = blockIdx.x;
    int dchunk = blk & 3;
    int lc = (blk >> 2) & 7;
    int b = blk >> 5;
    int d = dchunk * 256 + tid;
    float4 wv = *(const float4*)(w + (size_t)d * 4);
    float bias = bvec[d];
    int l0 = lc * 128;
    const float* base = up + (size_t)b * Ln * DIN + d;
    float* obase = out + (size_t)b * Ln * DIN + d;
    float x0, x1, x2;
    if (l0 == 0) { x0 = 0.f; x1 = 0.f; x2 = 0.f; }
    else {
        x0 = base[(size_t)(l0 - 3) * DIN];
        x1 = base[(size_t)(l0 - 2) * DIN];
        x2 = base[(size_t)(l0 - 1) * DIN];
    }
#pragma unroll 4
    for (int l = l0; l < l0 + 128; l++) {
        float xin = base[(size_t)l * DIN];
        float a = fmaf(wv.x, x0, fmaf(wv.y, x1, fmaf(wv.z, x2, fmaf(wv.w, xin, bias))));
        obase[(size_t)l * DIN] = __fdividef(a, 1.f + __expf(-a));
        x0 = x1; x1 = x2; x2 = xin;
    }
}

// ---------------------------------------------------------------------------
// Selective scan + skip + gating.
// ---------------------------------------------------------------------------
__device__ __forceinline__ float softplus_f(float x) {
    return (x > 20.f) ? x : __logf(1.f + __expf(x));
}

__global__ void __launch_bounds__(256) scan_kernel(
    const float* __restrict__ u, const float* __restrict__ dtl,
    const float* __restrict__ xdbl, const float* __restrict__ A_log,
    const float* __restrict__ Dw, const float* __restrict__ z,
    float* __restrict__ Y)
{
    int tid = threadIdx.x;
    int b = blockIdx.x >> 4;
    int d = ((blockIdx.x & 15) << 6) + (tid >> 2);
    int sg = tid & 3;                       // states sg*4 .. sg*4+3

    float A0 = -__expf(A_log[(size_t)d * DS + sg * 4 + 0]);
    float A1 = -__expf(A_log[(size_t)d * DS + sg * 4 + 1]);
    float A2 = -__expf(A_log[(size_t)d * DS + sg * 4 + 2]);
    float A3 = -__expf(A_log[(size_t)d * DS + sg * 4 + 3]);
    float Dv = Dw[d];

    const float* ub = u   + (size_t)b * Ln * DIN + d;
    const float* db = dtl + (size_t)b * Ln * DIN + d;
    const float* xb = xdbl + (size_t)b * Ln * 64;

    float h0 = 0.f, h1 = 0.f, h2 = 0.f, h3 = 0.f;

#pragma unroll 4
    for (int t = 0; t < TST; t++) {
        float uv = __ldg(ub + (size_t)t * DIN);
        float dv = __ldg(db + (size_t)t * DIN);
        float4 Bv = *(const float4*)(xb + (size_t)t * 64 + 32 + sg * 4);
        float dt = softplus_f(dv);
        float dtu = dt * uv;
        h0 = fmaf(h0, __expf(dt * A0), dtu * Bv.x);
        h1 = fmaf(h1, __expf(dt * A1), dtu * Bv.y);
        h2 = fmaf(h2, __expf(dt * A2), dtu * Bv.z);
        h3 = fmaf(h3, __expf(dt * A3), dtu * Bv.w);
    }
#pragma unroll 2
    for (int t = TST; t < Ln; t++) {
        float uv = __ldg(ub + (size_t)t * DIN);
        float dv = __ldg(db + (size_t)t * DIN);
        float4 Bv = *(const float4*)(xb + (size_t)t * 64 + 32 + sg * 4);
        float dt = softplus_f(dv);
        float dtu = dt * uv;
        h0 = fmaf(h0, __expf(dt * A0), dtu * Bv.x);
        h1 = fmaf(h1, __expf(dt * A1), dtu * Bv.y);
        h2 = fmaf(h2, __expf(dt * A2), dtu * Bv.z);
        h3 = fmaf(h3, __expf(dt * A3), dtu * Bv.w);
        float4 Cv = *(const float4*)(xb + (size_t)t * 64 + 48 + sg * 4);
        float y = fmaf(h0, Cv.x, fmaf(h1, Cv.y, fmaf(h2, Cv.z, h3 * Cv.w)));
        y += __shfl_xor_sync(0xffffffffu, y, 1);
        y += __shfl_xor_sync(0xffffffffu, y, 2);
        if (sg == 0) {
            int i = t - TST;
            size_t oidx = ((size_t)b * PRED + i) * DIN + d;
            float zv = z[oidx];
            float g = __fdividef(zv, 1.f + __expf(-zv));   // silu(z)
            Y[oidx] = (y + uv * Dv) * g;
        }
    }
}

// ---------------------------------------------------------------------------
// Head: out[b,i,c] = (Y[b,i,:] . wohT[c,:]) * std[b,c] + mean[b,c]
// ---------------------------------------------------------------------------
__global__ void head_kernel(const float* __restrict__ Y, const float* __restrict__ wohT,
                            const float* __restrict__ stdv, const float* __restrict__ meanv,
                            float* __restrict__ out)
{
    int bi = blockIdx.x;                // 0..1535 = b*96 + i
    int b = bi / PRED;
    int c = threadIdx.x >> 5;           // 0..20
    int lane = threadIdx.x & 31;
    const float* yr = Y + (size_t)bi * DIN;
    const float* wr = wohT + (size_t)c * DIN;
    float s = 0.f;
#pragma unroll 4
    for (int k = lane; k < DIN; k += 32) s = fmaf(yr[k], wr[k], s);
#pragma unroll
    for (int o = 16; o; o >>= 1) s += __shfl_xor_sync(0xffffffffu, s, o);
    if (lane == 0)
        out[(size_t)bi * Cout + c] = s * stdv[b * Cin + c] + meanv[b * Cin + c];
}

// ---------------------------------------------------------------------------
// Launch
// ---------------------------------------------------------------------------
extern "C" void kernel_launch(void* const* d_in, const int* in_sizes, int n_in,
                              void* d_out, int out_size)
{
    const float* x_enc   = (const float*)d_in[0];
    const float* x_mark  = (const float*)d_in[1];
    const float* ctw     = (const float*)d_in[2];   // [3,21,512]
    const float* tw      = (const float*)d_in[3];   // [4,512]
    const float* W_in    = (const float*)d_in[4];   // [512,2048]
    const float* conv_w  = (const float*)d_in[5];   // [1024,4]
    const float* conv_b  = (const float*)d_in[6];   // [1024]
    const float* W_xproj = (const float*)d_in[7];   // [1024,64]
    const float* W_dt    = (const float*)d_in[8];   // [32,1024]
    const float* b_dt    = (const float*)d_in[9];   // [1024]
    const float* A_log   = (const float*)d_in[10];  // [1024,16]
    const float* Dw      = (const float*)d_in[11];  // [1024]
    const float* W_out   = (const float*)d_in[12];  // [1024,512]
    const float* W_head  = (const float*)d_in[13];  // [512,21]
    float* out = (float*)d_out;

    float* S;
    cudaGetSymbolAddress((void**)&S, g_scratch);
    float* pe    = S + O_PE;
    float* meanv = S + O_MEAN;
    float* stdv  = S + O_STD;
    float* rstd  = S + O_RSTD;
    float* wohT  = S + O_WOHT;
    float* xnw   = S + O_XNW;
    float* Aemb  = S + O_AEMB;
    float* Bemb  = S + O_BEMB;
    float* emb   = S + O_EMB;
    float* u_pre = S + O_UPRE;
    float* u     = S + O_U;
    float* zbuf  = S + O_Z;
    float* xdbl  = S + O_XDBL;
    float* dtl   = S + O_DTL;
    float* Ybuf  = S + O_Y;

    const int IDENT = 1 << 30;

    // Preprocessing
    pe_kernel<<<2048, 256>>>(pe);
    stats_kernel<<<Bn * Cin, 128>>>(x_enc, meanv, stdv, rstd);
    woh_kernel<<<84, 256>>>(W_out, W_head, wohT);
    normalize_kernel<<<1344, 256>>>(x_enc, meanv, rstd, xnw);
    aemb_kernel<<<5120, 256>>>(xnw, x_mark, Aemb);
    bemb_kernel<<<160, 256>>>(ctw, tw, Bemb);

    // emb = Aemb[16384,80] @ Bemb[80,512] + PE   (fp32)
    sgemm_kernel<<<dim3(512 / 64, 16384 / 128), 256>>>(
        Aemb, 80, Bemb, 512, emb, 512, 80, nullptr, pe, 2, IDENT, 0, 0);

    // u_pre = emb @ W_in[:, :1024]    (tf32 tensor cores)
    tf32_gemm_kernel<<<dim3(1024 / 128, 16384 / 128), 256>>>(
        emb, 512, W_in, 2048, u_pre, 1024, 512, IDENT, 0, 0);

    // z (last 96 rows per batch) = emb_gathered @ W_in[:, 1024:]  (tf32)
    tf32_gemm_kernel<<<dim3(1024 / 128, 1536 / 128), 256>>>(
        emb, 512, W_in + 1024, 2048, zbuf, 1024, 512, PRED, TST, Ln);

    // depthwise causal conv + SiLU
    dwconv_kernel<<<512, 256>>>(u_pre, conv_w, conv_b, u);

    // x_dbl = u @ W_xproj  (fp32, N=64)
    sgemm_kernel<<<dim3(64 / 64, 16384 / 128), 256>>>(
        u, 1024, W_xproj, 64, xdbl, 64, 1024, nullptr, nullptr, 0, IDENT, 0, 0);

    // dt logits = dtr @ W_dt + b_dt   (fp32, K=32)
    sgemm_kernel<<<dim3(1024 / 64, 16384 / 128), 256>>>(
        xdbl, 64, W_dt, 1024, dtl, 1024, 32, b_dt, nullptr, 1, IDENT, 0, 0);

    // selective scan + skip + SiLU(z) gating -> Y [1536, 1024]
    scan_kernel<<<256, 256>>>(u, dtl, xdbl, A_log, Dw, zbuf, Ybuf);

    // head: (Y @ (W_out@W_head)) * std + mean
    head_kernel<<<1536, 672>>>(Ybuf, wohT, stdv, meanv, out);
}